// round 15
// baseline (speedup 1.0000x reference)
#include <cuda_runtime.h>
#include <cuda_bf16.h>
#include <cstdint>

#define Bv 256
#define Mv 1024
#define Dv 128
#define Nv 26
#define EP 32   // padded per-row stride for emission scratch

// ---------------- scratch ----------------
__device__ __nv_bfloat16 g_e[(size_t)Bv * Mv * EP];   // 16 MB emissions (bf16, padded)
__device__ float g_lp[Bv];                      // per-sequence log-probs
__device__ int   g_flag[Bv * 8];                // per-(seq,tile) ready flags

__device__ __forceinline__ void ffma2(unsigned long long &d,
                                      unsigned long long a,
                                      unsigned long long b) {
    asm("fma.rn.f32x2 %0, %1, %2, %0;" : "+l"(d) : "l"(a), "l"(b));
}
__device__ __forceinline__ void fadd2(unsigned long long &d, unsigned long long a) {
    asm("add.rn.f32x2 %0, %0, %1;" : "+l"(d) : "l"(a));
}
__device__ __forceinline__ unsigned long long packf2(float lo, float hi) {
    unsigned long long r;
    asm("mov.b64 %0, {%1, %2};" : "=l"(r) : "f"(lo), "f"(hi));
    return r;
}
__device__ __forceinline__ void waitflag(int idx) {
    unsigned v;
    do {
        asm volatile("ld.acquire.gpu.b32 %0, [%1];"
                     : "=r"(v) : "l"(g_flag + idx) : "memory");
        if (!v) __nanosleep(128);
    } while (!v);
}

// ---------------- Kernel 0: clear flags ----------------
__global__ void clear_kernel() {
    g_flag[blockIdx.x * 256 + threadIdx.x] = 0;
}

// ---------------- Kernel 1: emissions (R12-shape blocks, wave-ordered tiles) -----
// 2048 independent blocks. Wave w = b>>8 (256 blocks) produces tile
// order[w] = 0,7,1,6,2,5,3,4 for every sequence s = b&255.
__global__ void __launch_bounds__(256) emis_kernel(const float* __restrict__ X,
                                                   const float* __restrict__ W) {
    asm volatile("griddepcontrol.launch_dependents;");
    __shared__ __align__(16) unsigned short sX[128 * 136];   // 34816 B
    __shared__ __align__(16) unsigned short sW[32 * 136];    //  8704 B
    const int tid  = threadIdx.x;
    const int warp = tid >> 5, lane = tid & 31;
    const int g = lane >> 2, t = lane & 3;

    const int w  = blockIdx.x >> 8;
    const int s  = blockIdx.x & 255;
    const int tt = (w & 1) ? (7 - (w >> 1)) : (w >> 1);
    const size_t brow = (size_t)s * 1024 + tt * 128;

    for (int i = tid; i < 1664; i += 256) {
        const float2 w2 = reinterpret_cast<const float2*>(W)[i];
        const int row = i >> 6;
        const int cp  = i & 63;
        unsigned u;
        asm("cvt.rn.bf16x2.f32 %0, %1, %2;" : "=r"(u) : "f"(w2.y), "f"(w2.x));
        *reinterpret_cast<unsigned*>(&sW[row * 136 + cp * 2]) = u;
    }
    for (int i = tid; i < 6 * 68; i += 256)
        *reinterpret_cast<unsigned*>(&sW[26 * 136 + i * 2]) = 0;

    // X tile: 128 rows x 128 dims; 16 float4/thread in 4 batches of 4 (MLP=4)
    const float4* __restrict__ Xv =
        reinterpret_cast<const float4*>(X) + brow * 32;
#pragma unroll
    for (int ii = 0; ii < 4; ii++) {
        float4 v[4];
#pragma unroll
        for (int p = 0; p < 4; p++)
            v[p] = __ldcs(&Xv[tid + (ii * 4 + p) * 256]);
#pragma unroll
        for (int p = 0; p < 4; p++) {
            const int i = tid + (ii * 4 + p) * 256;
            const int row = i >> 5, q = i & 31;
            unsigned u0, u1;
            asm("cvt.rn.bf16x2.f32 %0, %1, %2;" : "=r"(u0) : "f"(v[p].y), "f"(v[p].x));
            asm("cvt.rn.bf16x2.f32 %0, %1, %2;" : "=r"(u1) : "f"(v[p].w), "f"(v[p].z));
            *reinterpret_cast<uint2*>(&sX[row * 136 + q * 4]) = make_uint2(u0, u1);
        }
    }
    __syncthreads();

    float d[4][4];
#pragma unroll
    for (int n = 0; n < 4; n++)
#pragma unroll
        for (int r = 0; r < 4; r++) d[n][r] = 0.0f;

    const unsigned* sXu = reinterpret_cast<const unsigned*>(sX);
    const unsigned* sWu = reinterpret_cast<const unsigned*>(sW);
    const int abase = ((16 * warp + g) * 272 + t * 4) >> 2;

#pragma unroll
    for (int k = 0; k < 8; k++) {
        const unsigned a0 = sXu[abase + k * 8];
        const unsigned a1 = sXu[abase + k * 8 + 544];
        const unsigned a2 = sXu[abase + k * 8 + 4];
        const unsigned a3 = sXu[abase + k * 8 + 548];
#pragma unroll
        for (int n = 0; n < 4; n++) {
            const int bbase = ((n * 8 + g) * 272 + k * 32 + t * 4) >> 2;
            const unsigned b0 = sWu[bbase];
            const unsigned b1 = sWu[bbase + 4];
            asm volatile(
                "mma.sync.aligned.m16n8k16.row.col.f32.bf16.bf16.f32 "
                "{%0,%1,%2,%3}, {%4,%5,%6,%7}, {%8,%9}, {%0,%1,%2,%3};"
                : "+f"(d[n][0]), "+f"(d[n][1]), "+f"(d[n][2]), "+f"(d[n][3])
                : "r"(a0), "r"(a1), "r"(a2), "r"(a3), "r"(b0), "r"(b1));
        }
    }

    unsigned short* eout =
        reinterpret_cast<unsigned short*>(g_e) + brow * EP;
    const int r0 = 16 * warp + g;
#pragma unroll
    for (int n = 0; n < 4; n++) {
        const int c = n * 8 + 2 * t;
        unsigned u01, u23;
        asm("cvt.rn.bf16x2.f32 %0, %1, %2;" : "=r"(u01) : "f"(d[n][1]), "f"(d[n][0]));
        asm("cvt.rn.bf16x2.f32 %0, %1, %2;" : "=r"(u23) : "f"(d[n][3]), "f"(d[n][2]));
        *reinterpret_cast<unsigned*>(&eout[(size_t)r0 * EP + c]) = u01;
        *reinterpret_cast<unsigned*>(&eout[(size_t)(r0 + 8) * EP + c]) = u23;
    }

    __threadfence();
    __syncthreads();
    if (tid == 0)
        asm volatile("st.release.gpu.b32 [%0], %1;"
                     :: "l"(g_flag + (s * 8 + tt)), "r"(1) : "memory");
}

// ---------------- Kernel 2: fwd/bwd scan (tile waits) + gather + epilogue -------
static __device__ __forceinline__ float mv26(unsigned src,
                                             const unsigned long long* eT) {
    unsigned long long p0, p1, p2, p3, p4, p5, p6, p7, p8, p9, pa, pb, pc;
    asm volatile("ld.volatile.shared.v2.b64 {%0,%1}, [%2];"
                 : "=l"(p0), "=l"(p1) : "r"(src));
    asm volatile("ld.volatile.shared.v2.b64 {%0,%1}, [%2];"
                 : "=l"(p2), "=l"(p3) : "r"(src + 16));
    asm volatile("ld.volatile.shared.v2.b64 {%0,%1}, [%2];"
                 : "=l"(p4), "=l"(p5) : "r"(src + 32));
    asm volatile("ld.volatile.shared.v2.b64 {%0,%1}, [%2];"
                 : "=l"(p6), "=l"(p7) : "r"(src + 48));
    asm volatile("ld.volatile.shared.v2.b64 {%0,%1}, [%2];"
                 : "=l"(p8), "=l"(p9) : "r"(src + 64));
    asm volatile("ld.volatile.shared.v2.b64 {%0,%1}, [%2];"
                 : "=l"(pa), "=l"(pb) : "r"(src + 80));
    asm volatile("ld.volatile.shared.b64 %0, [%1];"
                 : "=l"(pc) : "r"(src + 96));
    unsigned long long a0 = 0, a1 = 0, a2 = 0, a3 = 0;
    ffma2(a0, p0, eT[0]);  ffma2(a1, p1, eT[1]);
    ffma2(a2, p2, eT[2]);  ffma2(a3, p3, eT[3]);
    ffma2(a0, p4, eT[4]);  ffma2(a1, p5, eT[5]);
    ffma2(a2, p6, eT[6]);  ffma2(a3, p7, eT[7]);
    ffma2(a0, p8, eT[8]);  ffma2(a1, p9, eT[9]);
    ffma2(a2, pa, eT[10]); ffma2(a3, pb, eT[11]);
    ffma2(a0, pc, eT[12]);
    fadd2(a0, a1); fadd2(a2, a3); fadd2(a0, a2);
    float lo, hi;
    asm("mov.b64 {%0, %1}, %2;" : "=f"(lo), "=f"(hi) : "l"(a0));
    return lo + hi;
}

__device__ __forceinline__ void stsv(unsigned a, float v) {
    asm volatile("st.volatile.shared.f32 [%0], %1;" :: "r"(a), "f"(v));
}
__device__ __forceinline__ void rescale(float v, float &carry, int &eAcc) {
    const unsigned mb = __reduce_max_sync(0xffffffffu, __float_as_uint(v));
    const unsigned pb = mb & 0x7f800000u;
    carry = __uint_as_float(0x7f000000u - pb);       // exact 2^(127-E)
    eAcc += (int)(pb >> 23) - 127;
}

__global__ void __launch_bounds__(192) scan_kernel(const int* __restrict__ labels,
                                                   const float* __restrict__ T) {
    __shared__ __align__(16) float fbuf[4][2][32];
    __shared__ float sm_pF[2][32], sm_pB[2][32];
    __shared__ float sm_un[2];
    __shared__ int   sm_eA[2][2];
    const int warp = threadIdx.x >> 5;
    const int lane = threadIdx.x & 31;
    const unsigned FULL = 0xffffffffu;

    if (warp >= 4) {
        // unnorm gather, tiles consumed in production order 0,7,1,6,2,5,3,4
        const int pi = warp - 4;
        const int s = blockIdx.x * 2 + pi;
        const int* __restrict__ lab = labels + s * Mv;
        const __nv_bfloat16* __restrict__ eb = g_e + (size_t)s * Mv * EP;
        float un = 0.0f;
        for (int wv = 0; wv < 8; wv++) {
            const int tt = (wv & 1) ? (7 - (wv >> 1)) : (wv >> 1);
            waitflag(s * 8 + tt);
#pragma unroll
            for (int kk = 0; kk < 4; kk++) {
                const int i = (tt * 4 + kk) * 32 + lane;
                const int y = __ldg(&lab[i]);
                float v = __bfloat162float(eb[(size_t)i * EP + y]);
                if (i < Mv - 1)
                    v += __ldg(&T[y * Nv + __ldg(&lab[i + 1])]);
                un += v;
            }
        }
#pragma unroll
        for (int o = 16; o; o >>= 1) un += __shfl_xor_sync(FULL, un, o);
        if (lane == 0) sm_un[pi] = un;
    } else {
        const int pi  = warp >> 1;
        const int s   = blockIdx.x * 2 + pi;
        const int dir = warp & 1;
        const __nv_bfloat16* __restrict__ eseq = g_e + (size_t)s * Mv * EP + lane;

        const unsigned base0 =
            (unsigned)__cvta_generic_to_shared(&fbuf[warp][0][0]);
        unsigned srcA = base0, dstA = base0 + 128;

        unsigned long long expT2[13];
        float epE[8];
        float carry = 1.0f;
        int   eAcc = 0;

        if (dir == 0) {
            // forward: f_i = expE_i*(expT^T f_{i-1}); i=1..511; output f_511 (tiles 0-3)
#pragma unroll
            for (int k = 0; k < 13; k++)
                expT2[k] = (lane < Nv)
                    ? packf2(__expf(__ldg(&T[(2 * k) * Nv + lane])),
                             __expf(__ldg(&T[(2 * k + 1) * Nv + lane])))
                    : 0ull;

            waitflag(s * 8 + 0);
            const float e0 = __bfloat162float(eseq[0]);
            stsv(srcA + lane * 4, (lane < Nv) ? __expf(e0) : 0.0f);
#pragma unroll
            for (int k = 0; k < 8; k++)
                epE[k] = __expf(__bfloat162float(eseq[(size_t)(1 + k) * EP]));

            int tcur = 0;
            float fn = 0.0f;
            for (int gi = 0; gi < 63; gi++) {
                int mrow = gi * 8 + 16;
                if (mrow > 511) mrow = 511;
                const int tneed = mrow >> 7;
                while (tcur < tneed) { tcur++; waitflag(s * 8 + tcur); }
#pragma unroll
                for (int j = 0; j < 8; j++) {
                    const int i = 1 + gi * 8 + j;
                    const float expE = epE[j] * carry;
                    carry = 1.0f;
                    int pr = i + 8; if (pr > 511) pr = 511;
                    epE[j] = __expf(__bfloat162float(eseq[(size_t)pr * EP]));
                    fn = mv26(srcA, expT2) * expE;
                    stsv(dstA + lane * 4, fn);
                    const unsigned tmp = srcA; srcA = dstA; dstA = tmp;
                }
                rescale(fn, carry, eAcc);
            }
            // epilogue: i = 505..511 (7 steps)
#pragma unroll
            for (int j = 0; j < 7; j++) {
                const float expE = epE[j] * carry;
                carry = 1.0f;
                fn = mv26(srcA, expT2) * expE;
                stsv(dstA + lane * 4, fn);
                const unsigned tmp = srcA; srcA = dstA; dstA = tmp;
            }
            sm_pF[pi][lane] = fn;                      // f_511 (post-emission)
            if (lane == 0) sm_eA[pi][0] = eAcc;
        } else {
            // backward: h_1023 = expE_1023; h_i = expE_i*(expT h_{i+1}); i=1022..512;
            // then m_511 = expT * h_512 (tiles 7-4).
#pragma unroll
            for (int k = 0; k < 13; k++)
                expT2[k] = (lane < Nv)
                    ? packf2(__expf(__ldg(&T[lane * Nv + 2 * k])),
                             __expf(__ldg(&T[lane * Nv + 2 * k + 1])))
                    : 0ull;

            waitflag(s * 8 + 7);
            const float e1023 = __bfloat162float(eseq[(size_t)1023 * EP]);
            stsv(srcA + lane * 4, (lane < Nv) ? __expf(e1023) : 0.0f);
#pragma unroll
            for (int k = 0; k < 8; k++)
                epE[k] = __expf(__bfloat162float(eseq[(size_t)(1022 - k) * EP]));

            float h = 0.0f;
            // prologue: 7 steps, i = 1022..1016 (slots 0..6)
#pragma unroll
            for (int j = 0; j < 7; j++) {
                const int i = 1022 - j;
                const float expE = epE[j];
                epE[j] = __expf(__bfloat162float(eseq[(size_t)(i - 8) * EP]));
                h = mv26(srcA, expT2) * expE;
                stsv(dstA + lane * 4, h);
                const unsigned tmp = srcA; srcA = dstA; dstA = tmp;
            }
            rescale(h, carry, eAcc);

            int tcur = 7;
            for (int gi = 0; gi < 63; gi++) {
                int lrow = 1000 - gi * 8;
                if (lrow < 512) lrow = 512;
                const int tlow = lrow >> 7;
                while (tcur > tlow) { tcur--; waitflag(s * 8 + tcur); }
#pragma unroll
                for (int j = 0; j < 8; j++) {
                    const int i = 1015 - gi * 8 - j;
                    const int sl = (j + 7) & 7;
                    const float expE = epE[sl] * carry;
                    carry = 1.0f;
                    int pr = i - 8; if (pr < 512) pr = 512;
                    epE[sl] = __expf(__bfloat162float(eseq[(size_t)pr * EP]));
                    h = mv26(srcA, expT2) * expE;
                    stsv(dstA + lane * 4, h);
                    const unsigned tmp = srcA; srcA = dstA; dstA = tmp;
                }
                if (gi != 62) rescale(h, carry, eAcc);
            }
            const float m = mv26(srcA, expT2);         // m_511 = expT * h_512
            sm_pB[pi][lane] = m;
            if (lane == 0) sm_eA[pi][1] = eAcc;
        }
    }

    __syncthreads();

    // per-sequence epilogue: warps 0 and 2 finish their pair
    if (warp == 0 || warp == 2) {
        const int pi = warp >> 1;
        const int s = blockIdx.x * 2 + pi;
        float z = sm_pF[pi][lane] * sm_pB[pi][lane];   // lanes >= 26 are 0
#pragma unroll
        for (int o = 16; o; o >>= 1) z += __shfl_xor_sync(FULL, z, o);
        if (lane == 0) {
            g_lp[s] = sm_un[pi] - logf(z)
                      - (float)(sm_eA[pi][0] + sm_eA[pi][1]) * 0.6931471805599453f;
        }
    }
}

// ---------------- Kernel 3: final mean over 256 sequences ----------------
__global__ void __launch_bounds__(256) combine_kernel(float* __restrict__ out) {
    __shared__ float red[256];
    const int s = threadIdx.x;
    red[s] = g_lp[s];
    __syncthreads();
#pragma unroll
    for (int o = 128; o; o >>= 1) {
        if (s < o) red[s] += red[s + o];
        __syncthreads();
    }
    if (s == 0) out[0] = red[0] * (1.0f / Bv);
}

// ---------------- entry point ----------------
extern "C" void kernel_launch(void* const* d_in, const int* in_sizes, int n_in,
                              void* d_out, int out_size) {
    const float* X      = (const float*)d_in[0];
    const int*   labels = (const int*)  d_in[1];
    const float* W      = (const float*)d_in[2];
    const float* T      = (const float*)d_in[3];
    float* out = (float*)d_out;

    clear_kernel<<<8, 256>>>();
    emis_kernel<<<(Bv * Mv) / 128, 256>>>(X, W);

    // PDL launch: scan may start while emis is still producing tiles.
    cudaLaunchConfig_t cfg = {};
    cfg.gridDim = dim3(128);
    cfg.blockDim = dim3(192);
    cfg.dynamicSmemBytes = 0;
    cfg.stream = 0;
    cudaLaunchAttribute at[1];
    at[0].id = cudaLaunchAttributeProgrammaticStreamSerialization;
    at[0].val.programmaticStreamSerializationAllowed = 1;
    cfg.attrs = at;
    cfg.numAttrs = 1;
    cudaError_t e = cudaLaunchKernelEx(&cfg, scan_kernel, labels, T);
    if (e != cudaSuccess) {
        // fallback: plain serialized launch (flags all set by then)
        scan_kernel<<<128, 192>>>(labels, T);
    }

    combine_kernel<<<1, 256>>>(out);
}

// round 16
// speedup vs baseline: 1.1428x; 1.1428x over previous
#include <cuda_runtime.h>
#include <cuda_bf16.h>
#include <cstdint>

#define Bv 256
#define Mv 1024
#define Dv 128
#define Nv 26
#define EP 32   // padded per-row stride for emission scratch

// ---------------- scratch ----------------
__device__ __nv_bfloat16 g_e[(size_t)Bv * Mv * EP];   // 16 MB emissions (bf16, padded)
__device__ float g_lp[Bv];                      // per-sequence log-probs
__device__ int   g_done = 0;                    // completed scan blocks

__device__ __forceinline__ void ffma2(unsigned long long &d,
                                      unsigned long long a,
                                      unsigned long long b) {
    asm("fma.rn.f32x2 %0, %1, %2, %0;" : "+l"(d) : "l"(a), "l"(b));
}
__device__ __forceinline__ void fadd2(unsigned long long &d, unsigned long long a) {
    asm("add.rn.f32x2 %0, %0, %1;" : "+l"(d) : "l"(a));
}
__device__ __forceinline__ unsigned long long packf2(float lo, float hi) {
    unsigned long long r;
    asm("mov.b64 %0, {%1, %2};" : "=l"(r) : "f"(lo), "f"(hi));
    return r;
}

// ---------------- Kernel 1: emissions e = X @ W^T via HMMA bf16 (R14 exact) -----
__global__ void __launch_bounds__(256) emis_kernel(const float* __restrict__ X,
                                                   const float* __restrict__ W) {
    __shared__ __align__(16) unsigned short sX[128 * 136];   // 34816 B
    __shared__ __align__(16) unsigned short sW[32 * 136];    //  8704 B
    const int tid  = threadIdx.x;
    const int warp = tid >> 5, lane = tid & 31;
    const int g = lane >> 2, t = lane & 3;

    for (int i = tid; i < 1664; i += 256) {
        const float2 w2 = reinterpret_cast<const float2*>(W)[i];
        const int row = i >> 6;
        const int cp  = i & 63;
        unsigned u;
        asm("cvt.rn.bf16x2.f32 %0, %1, %2;" : "=r"(u) : "f"(w2.y), "f"(w2.x));
        *reinterpret_cast<unsigned*>(&sW[row * 136 + cp * 2]) = u;
    }
    for (int i = tid; i < 6 * 68; i += 256)
        *reinterpret_cast<unsigned*>(&sW[26 * 136 + i * 2]) = 0;

    // X tile: 128 rows x 128 dims; 16 float4/thread in 4 batches of 4 (MLP=4)
    const float4* __restrict__ Xv =
        reinterpret_cast<const float4*>(X) + (size_t)blockIdx.x * 128 * 32;
#pragma unroll
    for (int ii = 0; ii < 4; ii++) {
        float4 v[4];
#pragma unroll
        for (int p = 0; p < 4; p++)
            v[p] = __ldcs(&Xv[tid + (ii * 4 + p) * 256]);
#pragma unroll
        for (int p = 0; p < 4; p++) {
            const int i = tid + (ii * 4 + p) * 256;
            const int row = i >> 5, q = i & 31;
            unsigned u0, u1;
            asm("cvt.rn.bf16x2.f32 %0, %1, %2;" : "=r"(u0) : "f"(v[p].y), "f"(v[p].x));
            asm("cvt.rn.bf16x2.f32 %0, %1, %2;" : "=r"(u1) : "f"(v[p].w), "f"(v[p].z));
            *reinterpret_cast<uint2*>(&sX[row * 136 + q * 4]) = make_uint2(u0, u1);
        }
    }
    __syncthreads();

    float d[4][4];
#pragma unroll
    for (int n = 0; n < 4; n++)
#pragma unroll
        for (int r = 0; r < 4; r++) d[n][r] = 0.0f;

    const unsigned* sXu = reinterpret_cast<const unsigned*>(sX);
    const unsigned* sWu = reinterpret_cast<const unsigned*>(sW);
    const int arow  = 16 * warp + g;
    const int abase = (arow * 272 + t * 4) >> 2;

#pragma unroll
    for (int k = 0; k < 8; k++) {
        const unsigned a0 = sXu[abase + k * 8];
        const unsigned a1 = sXu[abase + k * 8 + 544];
        const unsigned a2 = sXu[abase + k * 8 + 4];
        const unsigned a3 = sXu[abase + k * 8 + 548];
#pragma unroll
        for (int n = 0; n < 4; n++) {
            const int bbase = ((n * 8 + g) * 272 + k * 32 + t * 4) >> 2;
            const unsigned b0 = sWu[bbase];
            const unsigned b1 = sWu[bbase + 4];
            asm volatile(
                "mma.sync.aligned.m16n8k16.row.col.f32.bf16.bf16.f32 "
                "{%0,%1,%2,%3}, {%4,%5,%6,%7}, {%8,%9}, {%0,%1,%2,%3};"
                : "+f"(d[n][0]), "+f"(d[n][1]), "+f"(d[n][2]), "+f"(d[n][3])
                : "r"(a0), "r"(a1), "r"(a2), "r"(a3), "r"(b0), "r"(b1));
        }
    }

    unsigned short* eout =
        reinterpret_cast<unsigned short*>(g_e) + (size_t)blockIdx.x * 128 * EP;
    const int r0 = 16 * warp + g;
#pragma unroll
    for (int n = 0; n < 4; n++) {
        const int c = n * 8 + 2 * t;
        unsigned u01, u23;
        asm("cvt.rn.bf16x2.f32 %0, %1, %2;" : "=r"(u01) : "f"(d[n][1]), "f"(d[n][0]));
        asm("cvt.rn.bf16x2.f32 %0, %1, %2;" : "=r"(u23) : "f"(d[n][3]), "f"(d[n][2]));
        *reinterpret_cast<unsigned*>(&eout[(size_t)r0 * EP + c]) = u01;
        *reinterpret_cast<unsigned*>(&eout[(size_t)(r0 + 8) * EP + c]) = u23;
    }
}

// ---------------- Kernel 2: scan + gather + epilogue + fused final mean ---------
static __device__ __forceinline__ float mv26(unsigned src,
                                             const unsigned long long* eT) {
    unsigned long long p0, p1, p2, p3, p4, p5, p6, p7, p8, p9, pa, pb, pc;
    asm volatile("ld.volatile.shared.v2.b64 {%0,%1}, [%2];"
                 : "=l"(p0), "=l"(p1) : "r"(src));
    asm volatile("ld.volatile.shared.v2.b64 {%0,%1}, [%2];"
                 : "=l"(p2), "=l"(p3) : "r"(src + 16));
    asm volatile("ld.volatile.shared.v2.b64 {%0,%1}, [%2];"
                 : "=l"(p4), "=l"(p5) : "r"(src + 32));
    asm volatile("ld.volatile.shared.v2.b64 {%0,%1}, [%2];"
                 : "=l"(p6), "=l"(p7) : "r"(src + 48));
    asm volatile("ld.volatile.shared.v2.b64 {%0,%1}, [%2];"
                 : "=l"(p8), "=l"(p9) : "r"(src + 64));
    asm volatile("ld.volatile.shared.v2.b64 {%0,%1}, [%2];"
                 : "=l"(pa), "=l"(pb) : "r"(src + 80));
    asm volatile("ld.volatile.shared.b64 %0, [%1];"
                 : "=l"(pc) : "r"(src + 96));
    unsigned long long a0 = 0, a1 = 0, a2 = 0, a3 = 0;
    ffma2(a0, p0, eT[0]);  ffma2(a1, p1, eT[1]);
    ffma2(a2, p2, eT[2]);  ffma2(a3, p3, eT[3]);
    ffma2(a0, p4, eT[4]);  ffma2(a1, p5, eT[5]);
    ffma2(a2, p6, eT[6]);  ffma2(a3, p7, eT[7]);
    ffma2(a0, p8, eT[8]);  ffma2(a1, p9, eT[9]);
    ffma2(a2, pa, eT[10]); ffma2(a3, pb, eT[11]);
    ffma2(a0, pc, eT[12]);
    fadd2(a0, a1); fadd2(a2, a3); fadd2(a0, a2);
    float lo, hi;
    asm("mov.b64 {%0, %1}, %2;" : "=f"(lo), "=f"(hi) : "l"(a0));
    return lo + hi;
}

__device__ __forceinline__ void stsv(unsigned a, float v) {
    asm volatile("st.volatile.shared.f32 [%0], %1;" :: "r"(a), "f"(v));
}

__global__ void __launch_bounds__(192) scan_kernel(const int* __restrict__ labels,
                                                   const float* __restrict__ T,
                                                   float* __restrict__ out) {
    __shared__ __align__(16) float fbuf[4][2][32];
    __shared__ float sm_pF[2][32], sm_pB[2][32];
    __shared__ float sm_un[2];
    __shared__ int   sm_eA[2][2];
    const int warp = threadIdx.x >> 5;
    const int lane = threadIdx.x & 31;
    const unsigned FULL = 0xffffffffu;

    if (warp >= 4) {
        // unnorm gather (one warp per sequence of the pair)
        const int pi = warp - 4;
        const int s = blockIdx.x * 2 + pi;
        const int* __restrict__ lab = labels + s * Mv;
        const __nv_bfloat16* __restrict__ eb = g_e + (size_t)s * Mv * EP;
        float un = 0.0f;
#pragma unroll 4
        for (int k = 0; k < 32; k++) {
            const int i = k * 32 + lane;
            const int y = __ldg(&lab[i]);
            float v = __bfloat162float(eb[(size_t)i * EP + y]);
            if (i < Mv - 1)
                v += __ldg(&T[y * Nv + __ldg(&lab[i + 1])]);
            un += v;
        }
#pragma unroll
        for (int o = 16; o; o >>= 1) un += __shfl_xor_sync(FULL, un, o);
        if (lane == 0) sm_un[pi] = un;
    } else {
        const int pi  = warp >> 1;
        const int s   = blockIdx.x * 2 + pi;
        const int dir = warp & 1;
        const __nv_bfloat16* __restrict__ eseq = g_e + (size_t)s * Mv * EP + lane;

        const unsigned base0 =
            (unsigned)__cvta_generic_to_shared(&fbuf[warp][0][0]);
        unsigned srcA = base0, dstA = base0 + 128;

        unsigned long long expT2[13];
        float epE[8];
        float carry = 1.0f;
        int   eAcc = 0;

        if (dir == 0) {
            // forward: f_i = expE_i * (expT^T f_{i-1}); i=1..512; pre-emission msum
#pragma unroll
            for (int k = 0; k < 13; k++)
                expT2[k] = (lane < Nv)
                    ? packf2(__expf(__ldg(&T[(2 * k) * Nv + lane])),
                             __expf(__ldg(&T[(2 * k + 1) * Nv + lane])))
                    : 0ull;

            const float e0 = __bfloat162float(eseq[0]);
            stsv(srcA + lane * 4, (lane < Nv) ? __expf(e0) : 0.0f);
#pragma unroll
            for (int k = 0; k < 8; k++)
                epE[k] = __expf(__bfloat162float(eseq[(size_t)(1 + k) * EP]));

            float msum = 0.0f;
            for (int gi = 0; gi < 64; gi++) {
#pragma unroll
                for (int j = 0; j < 8; j++) {
                    const int i = 1 + gi * 8 + j;
                    const float expE = epE[j] * carry;
                    carry = 1.0f;
                    epE[j] = __expf(__bfloat162float(eseq[(size_t)(i + 8) * EP]));
                    msum = mv26(srcA, expT2);
                    const float fn = msum * expE;
                    stsv(dstA + lane * 4, fn);
                    const unsigned tmp = srcA; srcA = dstA; dstA = tmp;
                    if (j == 7 && gi != 63) {
                        const unsigned mb = __reduce_max_sync(FULL, __float_as_uint(fn));
                        const unsigned pb = mb & 0x7f800000u;
                        carry = __uint_as_float(0x7f000000u - pb);   // exact 2^(127-E)
                        eAcc += (int)(pb >> 23) - 127;
                    }
                }
            }
            sm_pF[pi][lane] = msum;                     // pre-emission u_512
            if (lane == 0) sm_eA[pi][0] = eAcc;
        } else {
            // backward (h-form): h_1023 = expE_1023; h_i = expE_i*(expT h_{i+1}); i=1022..512
#pragma unroll
            for (int k = 0; k < 13; k++)
                expT2[k] = (lane < Nv)
                    ? packf2(__expf(__ldg(&T[lane * Nv + 2 * k])),
                             __expf(__ldg(&T[lane * Nv + 2 * k + 1])))
                    : 0ull;

            const float e1023 = __bfloat162float(eseq[(size_t)1023 * EP]);
            stsv(srcA + lane * 4, (lane < Nv) ? __expf(e1023) : 0.0f);
#pragma unroll
            for (int k = 0; k < 8; k++)
                epE[k] = __expf(__bfloat162float(eseq[(size_t)(1022 - k) * EP]));

            float h = 0.0f;
            // prologue: 7 steps, i = 1022..1016 (slots 0..6)
#pragma unroll
            for (int j = 0; j < 7; j++) {
                const int i = 1022 - j;
                const float expE = epE[j];
                epE[j] = __expf(__bfloat162float(eseq[(size_t)(i - 8) * EP]));
                h = mv26(srcA, expT2) * expE;
                stsv(dstA + lane * 4, h);
                const unsigned tmp = srcA; srcA = dstA; dstA = tmp;
            }
            {
                const unsigned mb = __reduce_max_sync(FULL, __float_as_uint(h));
                const unsigned pb = mb & 0x7f800000u;
                carry = __uint_as_float(0x7f000000u - pb);
                eAcc += (int)(pb >> 23) - 127;
            }
            // 63 groups of 8: i = 1015..512
            for (int gi = 0; gi < 63; gi++) {
#pragma unroll
                for (int j = 0; j < 8; j++) {
                    const int i = 1015 - gi * 8 - j;
                    const int sl = (j + 7) & 7;
                    const float expE = epE[sl] * carry;
                    carry = 1.0f;
                    epE[sl] = __expf(__bfloat162float(eseq[(size_t)(i - 8) * EP]));
                    h = mv26(srcA, expT2) * expE;
                    stsv(dstA + lane * 4, h);
                    const unsigned tmp = srcA; srcA = dstA; dstA = tmp;
                    if (j == 7 && gi != 62) {
                        const unsigned mb = __reduce_max_sync(FULL, __float_as_uint(h));
                        const unsigned pb = mb & 0x7f800000u;
                        carry = __uint_as_float(0x7f000000u - pb);
                        eAcc += (int)(pb >> 23) - 127;
                    }
                }
            }
            sm_pB[pi][lane] = h;                        // h_512 (post-emission)
            if (lane == 0) sm_eA[pi][1] = eAcc;
        }
    }

    __syncthreads();

    // per-sequence epilogue: warps 0 and 2 compute lp for their pair
    if (warp == 0 || warp == 2) {
        const int pi = warp >> 1;
        const int s = blockIdx.x * 2 + pi;
        float z = sm_pF[pi][lane] * sm_pB[pi][lane];    // lanes >= 26 are 0
#pragma unroll
        for (int o = 16; o; o >>= 1) z += __shfl_xor_sync(FULL, z, o);
        if (lane == 0) {
            g_lp[s] = sm_un[pi] - logf(z)
                      - (float)(sm_eA[pi][0] + sm_eA[pi][1]) * 0.6931471805599453f;
        }
    }

    // fused final mean: last block to finish reduces all 256 lp values
    __syncthreads();
    __shared__ int sm_last;
    if (threadIdx.x == 0) {
        __threadfence();
        sm_last = (atomicAdd(&g_done, 1) == gridDim.x - 1);
    }
    __syncthreads();
    if (sm_last && warp == 0) {
        float acc = 0.0f;
#pragma unroll
        for (int k = 0; k < 8; k++)
            acc += __ldcg(&g_lp[k * 32 + lane]);        // fixed order: deterministic
#pragma unroll
        for (int o = 16; o; o >>= 1) acc += __shfl_xor_sync(FULL, acc, o);
        if (lane == 0) {
            out[0] = acc * (1.0f / Bv);
            g_done = 0;                                  // reset for graph replay
        }
    }
}

// ---------------- entry point ----------------
extern "C" void kernel_launch(void* const* d_in, const int* in_sizes, int n_in,
                              void* d_out, int out_size) {
    const float* X      = (const float*)d_in[0];
    const int*   labels = (const int*)  d_in[1];
    const float* W      = (const float*)d_in[2];
    const float* T      = (const float*)d_in[3];
    float* out = (float*)d_out;

    emis_kernel<<<(Bv * Mv) / 128, 256>>>(X, W);
    scan_kernel<<<Bv / 2, 192>>>(labels, T, out);
}

// round 17
// speedup vs baseline: 1.1916x; 1.0427x over previous
#include <cuda_runtime.h>
#include <cuda_bf16.h>
#include <cstdint>

#define Bv 256
#define Mv 1024
#define Dv 128
#define Nv 26
#define EP 32   // padded per-row stride for emission scratch

// ---------------- scratch ----------------
__device__ __nv_bfloat16 g_e[(size_t)Bv * Mv * EP];   // 16 MB emissions (bf16, padded)
__device__ float g_lp[Bv];                      // per-sequence log-probs
__device__ int   g_done = 0;                    // completed scan blocks

__device__ __forceinline__ void ffma2(unsigned long long &d,
                                      unsigned long long a,
                                      unsigned long long b) {
    asm("fma.rn.f32x2 %0, %1, %2, %0;" : "+l"(d) : "l"(a), "l"(b));
}
__device__ __forceinline__ void fadd2(unsigned long long &d, unsigned long long a) {
    asm("add.rn.f32x2 %0, %0, %1;" : "+l"(d) : "l"(a));
}
__device__ __forceinline__ unsigned long long packf2(float lo, float hi) {
    unsigned long long r;
    asm("mov.b64 %0, {%1, %2};" : "=l"(r) : "f"(lo), "f"(hi));
    return r;
}
__device__ __forceinline__ unsigned bf2(float lo, float hi) {
    unsigned u;
    asm("cvt.rn.bf16x2.f32 %0, %1, %2;" : "=r"(u) : "f"(hi), "f"(lo));
    return u;
}

// ---------------- Kernel 1: emissions e = X @ W^T via HMMA bf16 -----------------
// A-fragments loaded DIRECTLY from global as float2 (8 full sectors per LDG.64),
// converted to bf16 at operand time. No X staging, no big smem, no block sync
// in the load path. W resident in smem (bf16, padded, zero-filled 26..31).
__global__ void __launch_bounds__(256) emis_kernel(const float* __restrict__ X,
                                                   const float* __restrict__ W) {
    __shared__ __align__(16) unsigned short sW[32 * 136];    // 8704 B
    const int tid  = threadIdx.x;
    const int warp = tid >> 5, lane = tid & 31;
    const int g = lane >> 2, t = lane & 3;

    for (int i = tid; i < 1664; i += 256) {
        const float2 w2 = reinterpret_cast<const float2*>(W)[i];
        const int row = i >> 6;
        const int cp  = i & 63;
        *reinterpret_cast<unsigned*>(&sW[row * 136 + cp * 2]) = bf2(w2.x, w2.y);
    }
    for (int i = tid; i < 6 * 68; i += 256)
        *reinterpret_cast<unsigned*>(&sW[26 * 136 + i * 2]) = 0;
    __syncthreads();

    const float2* __restrict__ Xb =
        reinterpret_cast<const float2*>(X) + (size_t)blockIdx.x * 128 * 64;
    const int r0 = 16 * warp + g;          // this lane's base row (and r0+8)

    // double-buffered A-fragment loads: 4 k-steps per buffer, 16 LDG.64 in flight
    float2 xa[2][4][4];                    // [buf][k][a0,a1,a2,a3]
#pragma unroll
    for (int k = 0; k < 4; k++) {
        const int c0 = k * 8 + t;          // float2 col index of {k*16+2t, +1}
        xa[0][k][0] = __ldcs(&Xb[(size_t)r0 * 64 + c0]);
        xa[0][k][1] = __ldcs(&Xb[(size_t)(r0 + 8) * 64 + c0]);
        xa[0][k][2] = __ldcs(&Xb[(size_t)r0 * 64 + c0 + 4]);
        xa[0][k][3] = __ldcs(&Xb[(size_t)(r0 + 8) * 64 + c0 + 4]);
    }

    float d[4][4];
#pragma unroll
    for (int n = 0; n < 4; n++)
#pragma unroll
        for (int r = 0; r < 4; r++) d[n][r] = 0.0f;

    const unsigned* sWu = reinterpret_cast<const unsigned*>(sW);

#pragma unroll
    for (int kb = 0; kb < 2; kb++) {
        if (kb == 0) {
#pragma unroll
            for (int k = 0; k < 4; k++) {
                const int c0 = (k + 4) * 8 + t;
                xa[1][k][0] = __ldcs(&Xb[(size_t)r0 * 64 + c0]);
                xa[1][k][1] = __ldcs(&Xb[(size_t)(r0 + 8) * 64 + c0]);
                xa[1][k][2] = __ldcs(&Xb[(size_t)r0 * 64 + c0 + 4]);
                xa[1][k][3] = __ldcs(&Xb[(size_t)(r0 + 8) * 64 + c0 + 4]);
            }
        }
#pragma unroll
        for (int kk = 0; kk < 4; kk++) {
            const int k = kb * 4 + kk;
            const unsigned a0 = bf2(xa[kb][kk][0].x, xa[kb][kk][0].y);
            const unsigned a1 = bf2(xa[kb][kk][1].x, xa[kb][kk][1].y);
            const unsigned a2 = bf2(xa[kb][kk][2].x, xa[kb][kk][2].y);
            const unsigned a3 = bf2(xa[kb][kk][3].x, xa[kb][kk][3].y);
#pragma unroll
            for (int n = 0; n < 4; n++) {
                const int bbase = ((n * 8 + g) * 272 + k * 32 + t * 4) >> 2;
                const unsigned b0 = sWu[bbase];
                const unsigned b1 = sWu[bbase + 4];
                asm volatile(
                    "mma.sync.aligned.m16n8k16.row.col.f32.bf16.bf16.f32 "
                    "{%0,%1,%2,%3}, {%4,%5,%6,%7}, {%8,%9}, {%0,%1,%2,%3};"
                    : "+f"(d[n][0]), "+f"(d[n][1]), "+f"(d[n][2]), "+f"(d[n][3])
                    : "r"(a0), "r"(a1), "r"(a2), "r"(a3), "r"(b0), "r"(b1));
            }
        }
    }

    unsigned short* eout =
        reinterpret_cast<unsigned short*>(g_e) + (size_t)blockIdx.x * 128 * EP;
#pragma unroll
    for (int n = 0; n < 4; n++) {
        const int c = n * 8 + 2 * t;
        *reinterpret_cast<unsigned*>(&eout[(size_t)r0 * EP + c]) =
            bf2(d[n][0], d[n][1]);
        *reinterpret_cast<unsigned*>(&eout[(size_t)(r0 + 8) * EP + c]) =
            bf2(d[n][2], d[n][3]);
    }
}

// ---------------- Kernel 2: scan + gather + epilogue + fused final mean ---------
static __device__ __forceinline__ float mv26(unsigned src,
                                             const unsigned long long* eT) {
    unsigned long long p0, p1, p2, p3, p4, p5, p6, p7, p8, p9, pa, pb, pc;
    asm volatile("ld.volatile.shared.v2.b64 {%0,%1}, [%2];"
                 : "=l"(p0), "=l"(p1) : "r"(src));
    asm volatile("ld.volatile.shared.v2.b64 {%0,%1}, [%2];"
                 : "=l"(p2), "=l"(p3) : "r"(src + 16));
    asm volatile("ld.volatile.shared.v2.b64 {%0,%1}, [%2];"
                 : "=l"(p4), "=l"(p5) : "r"(src + 32));
    asm volatile("ld.volatile.shared.v2.b64 {%0,%1}, [%2];"
                 : "=l"(p6), "=l"(p7) : "r"(src + 48));
    asm volatile("ld.volatile.shared.v2.b64 {%0,%1}, [%2];"
                 : "=l"(p8), "=l"(p9) : "r"(src + 64));
    asm volatile("ld.volatile.shared.v2.b64 {%0,%1}, [%2];"
                 : "=l"(pa), "=l"(pb) : "r"(src + 80));
    asm volatile("ld.volatile.shared.b64 %0, [%1];"
                 : "=l"(pc) : "r"(src + 96));
    unsigned long long a0 = 0, a1 = 0, a2 = 0, a3 = 0;
    ffma2(a0, p0, eT[0]);  ffma2(a1, p1, eT[1]);
    ffma2(a2, p2, eT[2]);  ffma2(a3, p3, eT[3]);
    ffma2(a0, p4, eT[4]);  ffma2(a1, p5, eT[5]);
    ffma2(a2, p6, eT[6]);  ffma2(a3, p7, eT[7]);
    ffma2(a0, p8, eT[8]);  ffma2(a1, p9, eT[9]);
    ffma2(a2, pa, eT[10]); ffma2(a3, pb, eT[11]);
    ffma2(a0, pc, eT[12]);
    fadd2(a0, a1); fadd2(a2, a3); fadd2(a0, a2);
    float lo, hi;
    asm("mov.b64 {%0, %1}, %2;" : "=f"(lo), "=f"(hi) : "l"(a0));
    return lo + hi;
}

__device__ __forceinline__ void stsv(unsigned a, float v) {
    asm volatile("st.volatile.shared.f32 [%0], %1;" :: "r"(a), "f"(v));
}

__global__ void __launch_bounds__(192) scan_kernel(const int* __restrict__ labels,
                                                   const float* __restrict__ T,
                                                   float* __restrict__ out) {
    __shared__ __align__(16) float fbuf[4][2][32];
    __shared__ float sm_pF[2][32], sm_pB[2][32];
    __shared__ float sm_un[2];
    __shared__ int   sm_eA[2][2];
    const int warp = threadIdx.x >> 5;
    const int lane = threadIdx.x & 31;
    const unsigned FULL = 0xffffffffu;

    if (warp >= 4) {
        // unnorm gather (one warp per sequence of the pair)
        const int pi = warp - 4;
        const int s = blockIdx.x * 2 + pi;
        const int* __restrict__ lab = labels + s * Mv;
        const __nv_bfloat16* __restrict__ eb = g_e + (size_t)s * Mv * EP;
        float un = 0.0f;
#pragma unroll 4
        for (int k = 0; k < 32; k++) {
            const int i = k * 32 + lane;
            const int y = __ldg(&lab[i]);
            float v = __bfloat162float(eb[(size_t)i * EP + y]);
            if (i < Mv - 1)
                v += __ldg(&T[y * Nv + __ldg(&lab[i + 1])]);
            un += v;
        }
#pragma unroll
        for (int o = 16; o; o >>= 1) un += __shfl_xor_sync(FULL, un, o);
        if (lane == 0) sm_un[pi] = un;
    } else {
        const int pi  = warp >> 1;
        const int s   = blockIdx.x * 2 + pi;
        const int dir = warp & 1;
        const __nv_bfloat16* __restrict__ eseq = g_e + (size_t)s * Mv * EP + lane;

        const unsigned base0 =
            (unsigned)__cvta_generic_to_shared(&fbuf[warp][0][0]);
        unsigned srcA = base0, dstA = base0 + 128;

        unsigned long long expT2[13];
        float epE[8];
        float carry = 1.0f;
        int   eAcc = 0;

        if (dir == 0) {
            // forward: f_i = expE_i * (expT^T f_{i-1}); i=1..512; pre-emission msum
#pragma unroll
            for (int k = 0; k < 13; k++)
                expT2[k] = (lane < Nv)
                    ? packf2(__expf(__ldg(&T[(2 * k) * Nv + lane])),
                             __expf(__ldg(&T[(2 * k + 1) * Nv + lane])))
                    : 0ull;

            const float e0 = __bfloat162float(eseq[0]);
            stsv(srcA + lane * 4, (lane < Nv) ? __expf(e0) : 0.0f);
#pragma unroll
            for (int k = 0; k < 8; k++)
                epE[k] = __expf(__bfloat162float(eseq[(size_t)(1 + k) * EP]));

            float msum = 0.0f;
            for (int gi = 0; gi < 64; gi++) {
#pragma unroll
                for (int j = 0; j < 8; j++) {
                    const int i = 1 + gi * 8 + j;
                    const float expE = epE[j] * carry;
                    carry = 1.0f;
                    epE[j] = __expf(__bfloat162float(eseq[(size_t)(i + 8) * EP]));
                    msum = mv26(srcA, expT2);
                    const float fn = msum * expE;
                    stsv(dstA + lane * 4, fn);
                    const unsigned tmp = srcA; srcA = dstA; dstA = tmp;
                    if (j == 7 && gi != 63) {
                        const unsigned mb = __reduce_max_sync(FULL, __float_as_uint(fn));
                        const unsigned pb = mb & 0x7f800000u;
                        carry = __uint_as_float(0x7f000000u - pb);   // exact 2^(127-E)
                        eAcc += (int)(pb >> 23) - 127;
                    }
                }
            }
            sm_pF[pi][lane] = msum;                     // pre-emission u_512
            if (lane == 0) sm_eA[pi][0] = eAcc;
        } else {
            // backward (h-form): h_1023 = expE_1023; h_i = expE_i*(expT h_{i+1}); i=1022..512
#pragma unroll
            for (int k = 0; k < 13; k++)
                expT2[k] = (lane < Nv)
                    ? packf2(__expf(__ldg(&T[lane * Nv + 2 * k])),
                             __expf(__ldg(&T[lane * Nv + 2 * k + 1])))
                    : 0ull;

            const float e1023 = __bfloat162float(eseq[(size_t)1023 * EP]);
            stsv(srcA + lane * 4, (lane < Nv) ? __expf(e1023) : 0.0f);
#pragma unroll
            for (int k = 0; k < 8; k++)
                epE[k] = __expf(__bfloat162float(eseq[(size_t)(1022 - k) * EP]));

            float h = 0.0f;
            // prologue: 7 steps, i = 1022..1016 (slots 0..6)
#pragma unroll
            for (int j = 0; j < 7; j++) {
                const int i = 1022 - j;
                const float expE = epE[j];
                epE[j] = __expf(__bfloat162float(eseq[(size_t)(i - 8) * EP]));
                h = mv26(srcA, expT2) * expE;
                stsv(dstA + lane * 4, h);
                const unsigned tmp = srcA; srcA = dstA; dstA = tmp;
            }
            {
                const unsigned mb = __reduce_max_sync(FULL, __float_as_uint(h));
                const unsigned pb = mb & 0x7f800000u;
                carry = __uint_as_float(0x7f000000u - pb);
                eAcc += (int)(pb >> 23) - 127;
            }
            // 63 groups of 8: i = 1015..512
            for (int gi = 0; gi < 63; gi++) {
#pragma unroll
                for (int j = 0; j < 8; j++) {
                    const int i = 1015 - gi * 8 - j;
                    const int sl = (j + 7) & 7;
                    const float expE = epE[sl] * carry;
                    carry = 1.0f;
                    epE[sl] = __expf(__bfloat162float(eseq[(size_t)(i - 8) * EP]));
                    h = mv26(srcA, expT2) * expE;
                    stsv(dstA + lane * 4, h);
                    const unsigned tmp = srcA; srcA = dstA; dstA = tmp;
                    if (j == 7 && gi != 62) {
                        const unsigned mb = __reduce_max_sync(FULL, __float_as_uint(h));
                        const unsigned pb = mb & 0x7f800000u;
                        carry = __uint_as_float(0x7f000000u - pb);
                        eAcc += (int)(pb >> 23) - 127;
                    }
                }
            }
            sm_pB[pi][lane] = h;                        // h_512 (post-emission)
            if (lane == 0) sm_eA[pi][1] = eAcc;
        }
    }

    __syncthreads();

    // per-sequence epilogue: warps 0 and 2 compute lp for their pair
    if (warp == 0 || warp == 2) {
        const int pi = warp >> 1;
        const int s = blockIdx.x * 2 + pi;
        float z = sm_pF[pi][lane] * sm_pB[pi][lane];    // lanes >= 26 are 0
#pragma unroll
        for (int o = 16; o; o >>= 1) z += __shfl_xor_sync(FULL, z, o);
        if (lane == 0) {
            g_lp[s] = sm_un[pi] - logf(z)
                      - (float)(sm_eA[pi][0] + sm_eA[pi][1]) * 0.6931471805599453f;
        }
    }

    // fused final mean: last block to finish reduces all 256 lp values
    __syncthreads();
    __shared__ int sm_last;
    if (threadIdx.x == 0) {
        __threadfence();
        sm_last = (atomicAdd(&g_done, 1) == gridDim.x - 1);
    }
    __syncthreads();
    if (sm_last && warp == 0) {
        float acc = 0.0f;
#pragma unroll
        for (int k = 0; k < 8; k++)
            acc += __ldcg(&g_lp[k * 32 + lane]);        // fixed order: deterministic
#pragma unroll
        for (int o = 16; o; o >>= 1) acc += __shfl_xor_sync(FULL, acc, o);
        if (lane == 0) {
            out[0] = acc * (1.0f / Bv);
            g_done = 0;                                  // reset for graph replay
        }
    }
}

// ---------------- entry point ----------------
extern "C" void kernel_launch(void* const* d_in, const int* in_sizes, int n_in,
                              void* d_out, int out_size) {
    const float* X      = (const float*)d_in[0];
    const int*   labels = (const int*)  d_in[1];
    const float* W      = (const float*)d_in[2];
    const float* T      = (const float*)d_in[3];
    float* out = (float*)d_out;

    emis_kernel<<<(Bv * Mv) / 128, 256>>>(X, W);
    scan_kernel<<<Bv / 2, 192>>>(labels, T, out);
}